// round 1
// baseline (speedup 1.0000x reference)
#include <cuda_runtime.h>

// Problem constants: B=8, H=8, S=1024, D=64
#define BH      64
#define SEQ     1024
#define HD      64
#define NROWS   (BH * SEQ)          // 65536 total (b,h,s) rows

// Scratch for projected q/k/v (allocation-free rule: __device__ globals)
__device__ float g_q[NROWS * HD];
__device__ float g_k[NROWS * HD];
__device__ float g_v[NROWS * HD];

// ---------------------------------------------------------------------------
// Projection: Y[r][e] = relu( sum_d X[r][d] * W[e][d] + bias[e] )
// One block = 64 rows x 64 outputs. 256 threads, 4x4 micro-tile per thread.
// ---------------------------------------------------------------------------
__global__ __launch_bounds__(256) void proj_kernel(
    const float* __restrict__ X, const float* __restrict__ W,
    const float* __restrict__ bias, int which)
{
    float* __restrict__ Y = (which == 0) ? g_q : (which == 1) ? g_k : g_v;

    __shared__ __align__(16) float Xs[64 * 64];
    __shared__ __align__(16) float Ws[64 * 64];

    const int tid = threadIdx.x;
    const size_t rowBase = (size_t)blockIdx.x * 64;

    // Stage X tile and full W into smem (float4, coalesced)
    {
        const float4* xs = (const float4*)(X + rowBase * HD);
        const float4* ws = (const float4*)W;
        float4* Xd = (float4*)Xs;
        float4* Wd = (float4*)Ws;
#pragma unroll
        for (int i = 0; i < 4; i++) {
            Xd[tid + i * 256] = xs[tid + i * 256];
            Wd[tid + i * 256] = ws[tid + i * 256];
        }
    }
    __syncthreads();

    const int tr = tid >> 4;    // 0..15 -> rows tr*4..tr*4+3
    const int tc = tid & 15;    // 0..15 -> cols tc*4..tc*4+3

    float acc[4][4] = {};
#pragma unroll
    for (int k = 0; k < 64; k += 4) {
        float4 a[4], b[4];
#pragma unroll
        for (int i = 0; i < 4; i++) a[i] = *(const float4*)&Xs[(tr * 4 + i) * 64 + k];
#pragma unroll
        for (int j = 0; j < 4; j++) b[j] = *(const float4*)&Ws[(tc * 4 + j) * 64 + k];
#pragma unroll
        for (int i = 0; i < 4; i++)
#pragma unroll
            for (int j = 0; j < 4; j++)
                acc[i][j] += a[i].x * b[j].x + a[i].y * b[j].y +
                             a[i].z * b[j].z + a[i].w * b[j].w;
    }

    const float4 bv = *(const float4*)&bias[tc * 4];
#pragma unroll
    for (int i = 0; i < 4; i++) {
        float4 o;
        o.x = fmaxf(acc[i][0] + bv.x, 0.0f);
        o.y = fmaxf(acc[i][1] + bv.y, 0.0f);
        o.z = fmaxf(acc[i][2] + bv.z, 0.0f);
        o.w = fmaxf(acc[i][3] + bv.w, 0.0f);
        *(float4*)&Y[(rowBase + tr * 4 + i) * HD + tc * 4] = o;
    }
}

// ---------------------------------------------------------------------------
// Attention: flash-style online softmax per (bh, 64-query tile).
//   score = softmax(q k^T / 8); a = score v
// Epilogue applies the reference's transpose(0,1,3,2)+reshape mangle and adds
// the raw-queries residual:  out[bh][lin] = a[lin & 1023][lin >> 10] + q_in[bh][lin]
// Static smem = exactly 48KB: Qs | KP (K, later reused for P) | Vs.
// Epilogue buffer As (64x65, conflict-free transpose) overlaps Qs+KP head.
// ---------------------------------------------------------------------------
__global__ __launch_bounds__(256) void attn_kernel(
    const float* __restrict__ queries_in, float* __restrict__ out)
{
    __shared__ __align__(16) float smem[12288];   // 48 KB
    float* Qs = smem;            // 64x64
    float* KP = smem + 4096;     // 64x64 : K tile, then P tile
    float* Vs = smem + 8192;     // 64x64
    float* As = smem;            // 64x65 = 4160 floats (overlaps Qs + KP[0:64])

    const int tid = threadIdx.x;
    const int tr = tid >> 4;
    const int tc = tid & 15;
    const int bh = blockIdx.y;
    const int qbase = blockIdx.x * 64;
    const size_t base = (size_t)bh * (SEQ * HD);

    // Load Q tile
    {
        const float4* src = (const float4*)(g_q + base + (size_t)qbase * HD);
        float4* dst = (float4*)Qs;
#pragma unroll
        for (int i = 0; i < 4; i++) dst[tid + i * 256] = src[tid + i * 256];
    }

    float m[4], l[4], o[4][4];
#pragma unroll
    for (int i = 0; i < 4; i++) {
        m[i] = -1e30f; l[i] = 0.0f;
#pragma unroll
        for (int j = 0; j < 4; j++) o[i][j] = 0.0f;
    }

    for (int kt = 0; kt < 16; kt++) {
        __syncthreads();   // previous iteration's PV reads of KP/Vs done
        {
            const float4* ks = (const float4*)(g_k + base + (size_t)kt * 64 * HD);
            const float4* vs = (const float4*)(g_v + base + (size_t)kt * 64 * HD);
            float4* kd = (float4*)KP;
            float4* vd = (float4*)Vs;
#pragma unroll
            for (int i = 0; i < 4; i++) {
                kd[tid + i * 256] = ks[tid + i * 256];
                vd[tid + i * 256] = vs[tid + i * 256];
            }
        }
        __syncthreads();

        // s[i][j] = sum_d Q[tr*4+i][d] * K[tc*4+j][d]
        float p[4][4] = {};
#pragma unroll
        for (int k = 0; k < 64; k += 4) {
            float4 a[4], b[4];
#pragma unroll
            for (int i = 0; i < 4; i++) a[i] = *(const float4*)&Qs[(tr * 4 + i) * 64 + k];
#pragma unroll
            for (int j = 0; j < 4; j++) b[j] = *(const float4*)&KP[(tc * 4 + j) * 64 + k];
#pragma unroll
            for (int i = 0; i < 4; i++)
#pragma unroll
                for (int j = 0; j < 4; j++)
                    p[i][j] += a[i].x * b[j].x + a[i].y * b[j].y +
                               a[i].z * b[j].z + a[i].w * b[j].w;
        }
        __syncthreads();   // everyone done reading KP (K) before P overwrites it

#pragma unroll
        for (int i = 0; i < 4; i++)
#pragma unroll
            for (int j = 0; j < 4; j++) p[i][j] *= 0.125f;   // 1/sqrt(64)

        // Online softmax update (rows tr*4+i live on the 16-lane group tc=0..15)
#pragma unroll
        for (int i = 0; i < 4; i++) {
            float tmax = fmaxf(fmaxf(p[i][0], p[i][1]), fmaxf(p[i][2], p[i][3]));
#pragma unroll
            for (int off = 8; off >= 1; off >>= 1)
                tmax = fmaxf(tmax, __shfl_xor_sync(0xffffffffu, tmax, off, 16));
            const float mn = fmaxf(m[i], tmax);
            const float al = __expf(m[i] - mn);
            float tsum = 0.0f;
#pragma unroll
            for (int j = 0; j < 4; j++) { p[i][j] = __expf(p[i][j] - mn); tsum += p[i][j]; }
#pragma unroll
            for (int off = 8; off >= 1; off >>= 1)
                tsum += __shfl_xor_sync(0xffffffffu, tsum, off, 16);
            l[i] = l[i] * al + tsum;
            m[i] = mn;
#pragma unroll
            for (int j = 0; j < 4; j++) o[i][j] *= al;
            *(float4*)&KP[(tr * 4 + i) * 64 + tc * 4] =
                make_float4(p[i][0], p[i][1], p[i][2], p[i][3]);
        }
        __syncthreads();

        // o[i][j] += sum_k P[tr*4+i][k] * V[k][tc*4+j]
#pragma unroll 4
        for (int k = 0; k < 64; k += 4) {
            const float4 v0 = *(const float4*)&Vs[(k + 0) * 64 + tc * 4];
            const float4 v1 = *(const float4*)&Vs[(k + 1) * 64 + tc * 4];
            const float4 v2 = *(const float4*)&Vs[(k + 2) * 64 + tc * 4];
            const float4 v3 = *(const float4*)&Vs[(k + 3) * 64 + tc * 4];
#pragma unroll
            for (int i = 0; i < 4; i++) {
                const float4 pi = *(const float4*)&KP[(tr * 4 + i) * 64 + k];
                o[i][0] += pi.x * v0.x + pi.y * v1.x + pi.z * v2.x + pi.w * v3.x;
                o[i][1] += pi.x * v0.y + pi.y * v1.y + pi.z * v2.y + pi.w * v3.y;
                o[i][2] += pi.x * v0.z + pi.y * v1.z + pi.z * v2.z + pi.w * v3.z;
                o[i][3] += pi.x * v0.w + pi.y * v1.w + pi.z * v2.w + pi.w * v3.w;
            }
        }
    }

    __syncthreads();   // last PV reads of KP done before As overwrites Qs/KP head

    // Normalize and stage into As (stride 65 -> conflict-free transpose reads)
#pragma unroll
    for (int i = 0; i < 4; i++) {
        const float inv = 1.0f / l[i];
#pragma unroll
        for (int j = 0; j < 4; j++)
            As[(tr * 4 + i) * 65 + tc * 4 + j] = o[i][j] * inv;
    }
    __syncthreads();

    // out[bh][lin] = a[s = lin&1023][d = lin>>10] + queries_in[bh][lin],
    // restricted to s in [qbase, qbase+64): lin = d*1024 + qbase + sl
    const float* qin = queries_in + (size_t)bh * (SEQ * HD);
    float* op = out + (size_t)bh * (SEQ * HD);
#pragma unroll
    for (int t = 0; t < 16; t++) {
        const int idx = tid + t * 256;       // 0..4095
        const int d  = idx >> 6;
        const int sl = idx & 63;
        const int lin = d * 1024 + qbase + sl;
        op[lin] = As[sl * 65 + d] + qin[lin];
    }
}

// ---------------------------------------------------------------------------
// Launch: inputs in metadata order:
//  0 queries, 1 keys, 2 values, 3 Wq_w, 4 Wq_b, 5 Wk_w, 6 Wk_b, 7 Wv_w, 8 Wv_b
// ---------------------------------------------------------------------------
extern "C" void kernel_launch(void* const* d_in, const int* in_sizes, int n_in,
                              void* d_out, int out_size)
{
    const float* q  = (const float*)d_in[0];
    const float* k  = (const float*)d_in[1];
    const float* v  = (const float*)d_in[2];
    const float* Wq = (const float*)d_in[3];
    const float* bq = (const float*)d_in[4];
    const float* Wk = (const float*)d_in[5];
    const float* bk = (const float*)d_in[6];
    const float* Wv = (const float*)d_in[7];
    const float* bv = (const float*)d_in[8];
    float* out = (float*)d_out;

    proj_kernel<<<1024, 256>>>(q, Wq, bq, 0);
    proj_kernel<<<1024, 256>>>(k, Wk, bk, 1);
    proj_kernel<<<1024, 256>>>(v, Wv, bv, 2);
    attn_kernel<<<dim3(16, 64), 256>>>(q, out);
}